// round 13
// baseline (speedup 1.0000x reference)
#include <cuda_runtime.h>
#include <cuda_fp16.h>
#include <cstdint>

#define B_ 8
#define C_ 256
#define H_ 128
#define W_ 128
#define HW_ (H_*W_)            // 16384
#define NPLANE (B_*C_)         // 2048
#define K_ 1280
#define O_ 256

#define NEG_INF __int_as_float(0xff800000)

// fp16 scratch: x copy + 4 directional-max tensors + transposed weights.
__device__ __half g_x16[NPLANE*HW_];
__device__ __half g_dir16[4][NPLANE*HW_];
__device__ __half g_wT16[K_*O_];

// ------------------------------------------------------------------
// helpers
// ------------------------------------------------------------------
__device__ __forceinline__ uint32_t smem_u32(const void* p) {
    return (uint32_t)__cvta_generic_to_shared(p);
}
__device__ __forceinline__ void cp16(uint32_t s, const void* g) {
    asm volatile("cp.async.cg.shared.global [%0], [%1], 16;\n" :: "r"(s), "l"(g));
}
__device__ __forceinline__ void ldsm_x4_t(uint32_t& d0, uint32_t& d1,
                                          uint32_t& d2, uint32_t& d3, uint32_t a) {
    asm volatile("ldmatrix.sync.aligned.m8n8.x4.trans.shared.b16 {%0,%1,%2,%3},[%4];\n"
                 : "=r"(d0), "=r"(d1), "=r"(d2), "=r"(d3) : "r"(a));
}
__device__ __forceinline__ void mma_f16(float* d, const uint32_t* a, const uint32_t* b) {
    asm volatile(
        "mma.sync.aligned.m16n8k16.row.col.f32.f16.f16.f32 "
        "{%0,%1,%2,%3},{%4,%5,%6,%7},{%8,%9},{%0,%1,%2,%3};"
        : "+f"(d[0]), "+f"(d[1]), "+f"(d[2]), "+f"(d[3])
        : "r"(a[0]), "r"(a[1]), "r"(a[2]), "r"(a[3]), "r"(b[0]), "r"(b[1]));
}
__device__ __forceinline__ uint32_t h2u(__half2 h) {
    return *reinterpret_cast<uint32_t*>(&h);
}
// streaming stores (evict-first): 4B and 8B
__device__ __forceinline__ void stcs4(void* p, uint32_t v) {
    asm volatile("st.global.cs.b32 [%0], %1;" :: "l"(p), "r"(v) : "memory");
}
__device__ __forceinline__ void stcs8(void* p, uint32_t v0, uint32_t v1) {
    asm volatile("st.global.cs.v2.b32 [%0], {%1,%2};" :: "l"(p), "r"(v0), "r"(v1) : "memory");
}

// ------------------------------------------------------------------
// kernel 0: transpose conv_w [O][K] -> wT16 [K][O]
// ------------------------------------------------------------------
__global__ void k_wt(const float* __restrict__ w) {
    int idx = blockIdx.x * 256 + threadIdx.x;
    if (idx < K_*O_) {
        int o = idx / K_;
        int k = idx - o*K_;
        g_wT16[k*O_ + o] = __float2half_rn(w[idx]);
    }
}

// ------------------------------------------------------------------
// kernel 1: all 4 directional maxes + x16, one plane per CTA, full grid.
// fp16 plane in smem; warps 0-1 H-prefix, 2-3 H-suffix, 4-7 W-scans
// with 2 rows in flight (interleaved shuffle chains). Streaming stores.
// ------------------------------------------------------------------
#define SP_LD 132   // halves per smem row (264B)

__global__ void __launch_bounds__(256) k_dir(const float* __restrict__ x) {
    __shared__ __half sp[H_*SP_LD];
    int plane = blockIdx.x;
    const float* src = x + (size_t)plane*HW_;
    __half* x16 = g_x16 + (size_t)plane*HW_;
    int tid = threadIdx.x;

    // ---- load: float4 -> fp16 smem + fp16 global copy ----
    #pragma unroll
    for (int i = 0; i < 16; ++i) {
        int c = tid + i*256;               // float4 index 0..4095
        int h = c >> 5, f4 = c & 31;
        float4 v = __ldg(reinterpret_cast<const float4*>(src) + c);
        __half2 a = __floats2half2_rn(v.x, v.y);
        __half2 b = __floats2half2_rn(v.z, v.w);
        uint32_t ua = h2u(a), ub = h2u(b);
        stcs8(x16 + (size_t)c*4, ua, ub);
        *reinterpret_cast<uint2*>(sp + h*SP_LD + f4*4) = make_uint2(ua, ub);
    }
    __syncthreads();

    int warp = tid >> 5, lane = tid & 31;
    const __half2 ninf2 = __floats2half2_rn(NEG_INF, NEG_INF);

    if (warp < 2) {
        int t = tid;                       // 0..63, column pair
        __half* d0 = g_dir16[0] + (size_t)plane*HW_;
        __half2 m = ninf2;
        #pragma unroll 8
        for (int h = 0; h < H_; ++h) {
            m = __hmax2(m, *reinterpret_cast<__half2*>(sp + h*SP_LD + 2*t));
            stcs4(d0 + h*W_ + 2*t, h2u(m));
        }
    } else if (warp < 4) {
        int t = tid - 64;
        __half* d1 = g_dir16[1] + (size_t)plane*HW_;
        __half2 m = ninf2;
        #pragma unroll 8
        for (int h = H_-1; h >= 0; --h) {
            m = __hmax2(m, *reinterpret_cast<__half2*>(sp + h*SP_LD + 2*t));
            stcs4(d1 + h*W_ + 2*t, h2u(m));
        }
    } else {
        // W-scans: warp handles 32 rows, TWO rows in flight per iteration
        __half* d2 = g_dir16[2] + (size_t)plane*HW_;
        __half* d3 = g_dir16[3] + (size_t)plane*HW_;
        int hbase = (warp - 4)*32;
        for (int r = 0; r < 16; ++r) {
            int ha = hbase + r, hb = hbase + 16 + r;
            uint2 ua = *reinterpret_cast<uint2*>(sp + ha*SP_LD + 4*lane);
            uint2 ub = *reinterpret_cast<uint2*>(sp + hb*SP_LD + 4*lane);
            float2 a0 = __half22float2(*reinterpret_cast<__half2*>(&ua.x));
            float2 a1 = __half22float2(*reinterpret_cast<__half2*>(&ua.y));
            float2 b0 = __half22float2(*reinterpret_cast<__half2*>(&ub.x));
            float2 b1 = __half22float2(*reinterpret_cast<__half2*>(&ub.y));

            // ---- prefix, both rows interleaved ----
            float pa0 = a0.x, pa1 = fmaxf(a0.y,pa0), pa2 = fmaxf(a1.x,pa1), pa3 = fmaxf(a1.y,pa2);
            float pb0 = b0.x, pb1 = fmaxf(b0.y,pb0), pb2 = fmaxf(b1.x,pb1), pb3 = fmaxf(b1.y,pb2);
            float aga = pa3, agb = pb3;
            #pragma unroll
            for (int d = 1; d < 32; d <<= 1) {
                float ta = __shfl_up_sync(0xffffffffu, aga, d);
                float tb = __shfl_up_sync(0xffffffffu, agb, d);
                if (lane >= d) { aga = fmaxf(aga, ta); agb = fmaxf(agb, tb); }
            }
            float pva = __shfl_up_sync(0xffffffffu, aga, 1);
            float pvb = __shfl_up_sync(0xffffffffu, agb, 1);
            if (lane == 0) { pva = NEG_INF; pvb = NEG_INF; }
            {
                __half2 A0 = __floats2half2_rn(fmaxf(pa0,pva), fmaxf(pa1,pva));
                __half2 A1 = __floats2half2_rn(fmaxf(pa2,pva), fmaxf(pa3,pva));
                __half2 B0 = __floats2half2_rn(fmaxf(pb0,pvb), fmaxf(pb1,pvb));
                __half2 B1 = __floats2half2_rn(fmaxf(pb2,pvb), fmaxf(pb3,pvb));
                stcs8(d2 + ha*W_ + 4*lane, h2u(A0), h2u(A1));
                stcs8(d2 + hb*W_ + 4*lane, h2u(B0), h2u(B1));
            }

            // ---- suffix, both rows interleaved ----
            float sa3 = a1.y, sa2 = fmaxf(a1.x,sa3), sa1 = fmaxf(a0.y,sa2), sa0 = fmaxf(a0.x,sa1);
            float sb3 = b1.y, sb2 = fmaxf(b1.x,sb3), sb1 = fmaxf(b0.y,sb2), sb0 = fmaxf(b0.x,sb1);
            float ag2a = sa0, ag2b = sb0;
            #pragma unroll
            for (int d = 1; d < 32; d <<= 1) {
                float ta = __shfl_down_sync(0xffffffffu, ag2a, d);
                float tb = __shfl_down_sync(0xffffffffu, ag2b, d);
                if (lane + d < 32) { ag2a = fmaxf(ag2a, ta); ag2b = fmaxf(ag2b, tb); }
            }
            float nxa = __shfl_down_sync(0xffffffffu, ag2a, 1);
            float nxb = __shfl_down_sync(0xffffffffu, ag2b, 1);
            if (lane == 31) { nxa = NEG_INF; nxb = NEG_INF; }
            {
                __half2 A0 = __floats2half2_rn(fmaxf(sa0,nxa), fmaxf(sa1,nxa));
                __half2 A1 = __floats2half2_rn(fmaxf(sa2,nxa), fmaxf(sa3,nxa));
                __half2 B0 = __floats2half2_rn(fmaxf(sb0,nxb), fmaxf(sb1,nxb));
                __half2 B1 = __floats2half2_rn(fmaxf(sb2,nxb), fmaxf(sb3,nxb));
                stcs8(d3 + ha*W_ + 4*lane, h2u(A0), h2u(A1));
                stcs8(d3 + hb*W_ + 4*lane, h2u(B0), h2u(B1));
            }
        }
    }
}

// ------------------------------------------------------------------
// kernel 2: fp16 GEMM, ALL batches in one launch (R10/R12-proven, unchanged).
// ------------------------------------------------------------------
#define BM 128
#define BN 256
#define BK 32
#define STAGES 3
#define SA_LD 136
#define SB_LD 264
#define STG_HALVES (BK*SA_LD + BK*SB_LD)
#define GEMM_SMEM (STAGES*STG_HALVES*2)   // 76800 B

__global__ void __launch_bounds__(256, 1) k_gemm(const float* __restrict__ bias,
                                                 float* __restrict__ out) {
    extern __shared__ __half sm[];

    int tid  = threadIdx.x;
    int lane = tid & 31, warp = tid >> 5;
    int wm = warp >> 2, wn = warp & 3;
    int grp = lane >> 2, tig = lane & 3;
    int lr = lane & 7, lg = lane >> 3;

    int pixbase = blockIdx.x * BM;
    int b       = blockIdx.y;

    size_t boff = (size_t)b * C_ * HW_;
    const __half* srcs[5] = { g_x16 + boff, g_dir16[0] + boff, g_dir16[1] + boff,
                              g_dir16[2] + boff, g_dir16[3] + boff };

    auto load_tile = [&](int kt, int st) {
        int region = kt >> 3;
        int c0 = (kt & 7) * BK;
        const __half* aptr = srcs[region] + (size_t)c0*HW_ + pixbase;
        const __half* bptr = g_wT16 + (size_t)(kt*BK)*O_;
        __half* sa = sm + st*STG_HALVES;
        __half* sb = sa + BK*SA_LD;
        #pragma unroll
        for (int i = 0; i < 2; ++i) {
            int c  = tid + i*256;
            int kr = c >> 4, cc = c & 15;
            cp16(smem_u32(sa + kr*SA_LD + cc*8), aptr + (size_t)kr*HW_ + cc*8);
        }
        #pragma unroll
        for (int i = 0; i < 4; ++i) {
            int c  = tid + i*256;
            int kr = c >> 5, cc = c & 31;
            cp16(smem_u32(sb + kr*SB_LD + cc*8), bptr + kr*O_ + cc*8);
        }
        asm volatile("cp.async.commit_group;\n" ::: "memory");
    };

    float acc[4][8][4];
    #pragma unroll
    for (int i = 0; i < 4; ++i)
        #pragma unroll
        for (int j = 0; j < 8; ++j)
            #pragma unroll
            for (int r = 0; r < 4; ++r) acc[i][j][r] = 0.f;

    load_tile(0, 0);
    load_tile(1, 1);

    for (int kt = 0; kt < 40; ++kt) {
        int cur = kt % STAGES;
        if (kt + 2 < 40) {
            load_tile(kt + 2, (kt + 2) % STAGES);
            asm volatile("cp.async.wait_group 2;\n" ::: "memory");
        } else {
            asm volatile("cp.async.wait_group %0;\n" :: "n"(0) : "memory");
        }
        __syncthreads();

        uint32_t saU = smem_u32(sm + cur*STG_HALVES);
        uint32_t sbU = saU + BK*SA_LD*2;

        uint32_t af[2][4][4];
        uint32_t bf[2][8][2];
        #pragma unroll
        for (int s = 0; s < 2; ++s) {
            int k0 = s*16;
            {
                int krow = k0 + lr + ((lg & 2) << 2);
                int cofs = (lg & 1) << 3;
                #pragma unroll
                for (int mf = 0; mf < 4; ++mf) {
                    int m0 = wm*64 + mf*16;
                    uint32_t a = saU + (uint32_t)(krow*SA_LD + m0 + cofs)*2;
                    ldsm_x4_t(af[s][mf][0], af[s][mf][1], af[s][mf][2], af[s][mf][3], a);
                }
            }
            {
                int krow = k0 + lr + ((lg & 1) << 3);
                int cofs = (lg >> 1) << 3;
                #pragma unroll
                for (int jp = 0; jp < 4; ++jp) {
                    int nj = wn*64 + jp*16;
                    uint32_t a = sbU + (uint32_t)(krow*SB_LD + nj + cofs)*2;
                    ldsm_x4_t(bf[s][2*jp][0], bf[s][2*jp][1],
                              bf[s][2*jp+1][0], bf[s][2*jp+1][1], a);
                }
            }
        }
        #pragma unroll
        for (int s = 0; s < 2; ++s)
            #pragma unroll
            for (int mf = 0; mf < 4; ++mf)
                #pragma unroll
                for (int nf = 0; nf < 8; ++nf)
                    mma_f16(acc[mf][nf], af[s][mf], bf[s][nf]);
        __syncthreads();
    }

    float* outb = out + (size_t)b * O_ * HW_;
    #pragma unroll
    for (int nf = 0; nf < 8; ++nf) {
        int o = wn*64 + nf*8 + tig*2;
        float bv0 = bias[o], bv1 = bias[o+1];
        #pragma unroll
        for (int mf = 0; mf < 4; ++mf) {
            int m = pixbase + wm*64 + mf*16 + grp;
            outb[(size_t)o*HW_ + m]         = acc[mf][nf][0] + bv0;
            outb[(size_t)(o+1)*HW_ + m]     = acc[mf][nf][1] + bv1;
            outb[(size_t)o*HW_ + m + 8]     = acc[mf][nf][2] + bv0;
            outb[(size_t)(o+1)*HW_ + m + 8] = acc[mf][nf][3] + bv1;
        }
    }
}

// ------------------------------------------------------------------
// launch: k_wt runs concurrently with k_dir on one extra stream
// (2 streams / 2 events total — well under the R7-proven budget).
// ------------------------------------------------------------------
extern "C" void kernel_launch(void* const* d_in, const int* in_sizes, int n_in,
                              void* d_out, int out_size) {
    (void)in_sizes; (void)n_in; (void)out_size;
    const float* x    = (const float*)d_in[0];
    const float* w    = (const float*)d_in[1];
    const float* bias = (const float*)d_in[2];
    float* out = (float*)d_out;

    static cudaStream_t sW = nullptr;
    static cudaEvent_t evFork, evW;
    if (!sW) {
        cudaStreamCreateWithFlags(&sW, cudaStreamNonBlocking);
        cudaEventCreateWithFlags(&evFork, cudaEventDisableTiming);
        cudaEventCreateWithFlags(&evW,    cudaEventDisableTiming);
        cudaFuncSetAttribute(k_gemm, cudaFuncAttributeMaxDynamicSharedMemorySize, GEMM_SMEM);
    }

    cudaEventRecord(evFork, 0);
    cudaStreamWaitEvent(sW, evFork, 0);
    k_wt<<<(K_*O_ + 255)/256, 256, 0, sW>>>(w);
    cudaEventRecord(evW, sW);

    k_dir<<<NPLANE, 256>>>(x);

    cudaStreamWaitEvent(0, evW, 0);
    dim3 grid(HW_/BM, B_);
    k_gemm<<<grid, 256, GEMM_SMEM>>>(bias, out);
}